// round 12
// baseline (speedup 1.0000x reference)
#include <cuda_runtime.h>
#include <cuda_fp16.h>
#include <math.h>

#define NMAX 50000
#define EMAX 800000

__device__ __forceinline__ float tanh_fast(float x) {
    float y;
    asm("tanh.approx.f32 %0, %1;" : "=f"(y) : "f"(x));
    return y;
}
__device__ __forceinline__ float sigmoid_fast(float x) {
    return 0.5f * tanh_fast(0.5f * x) + 0.5f;
}

#define MMA16816(d, a, b0_, b1_) \
    asm volatile("mma.sync.aligned.m16n8k16.row.col.f32.f16.f16.f32 " \
        "{%0,%1,%2,%3}, {%4,%5,%6,%7}, {%8,%9}, {%0,%1,%2,%3};" \
        : "+f"((d)[0]), "+f"((d)[1]), "+f"((d)[2]), "+f"((d)[3]) \
        : "r"((a)[0]), "r"((a)[1]), "r"((a)[2]), "r"((a)[3]), "r"(b0_), "r"(b1_))

// ---------------- scratch (device globals; zero-initialized at module load) ----------
__device__ __align__(16) float  g_gx[NMAX * 96];      // gconv(x), t-major: [t][node][8]
__device__ __align__(16) float  g_h0[NMAX * 64];
__device__ __align__(16) float  g_h1[NMAX * 64];
__device__ __align__(16) float  g_gpair[NMAX * 128];  // [gconv(h0) | gconv(h1)] fp32
__device__ __align__(16) float  g_grh[NMAX * 64];     // gconv(r*h) fp32
__device__ __align__(16) float  g_z[NMAX * 64];
__device__ __align__(8)  __half2 g_rh16[NMAX * 32];   // r*h, fp16 (gconv input)
__device__ __align__(16) uint2   g_hpk[NMAX * 32];    // packed {h0 half2, h1 half2} per lane
__device__ int   g_rowptr[NMAX + 1];
__device__ int   g_off[NMAX];
__device__ __align__(8) int2 g_edge[EMAX];            // (src, w bits)

// NOTE: h0/h1/gpair/hpk/rowptr must be zero at entry. Zero-initialized at module
// load; cleanup_kernel (last launch) re-zeroes them, so the invariant holds
// across the correctness call and every graph replay.

__global__ void hist_kernel(const int* __restrict__ dst, int E) {
    int e = blockIdx.x * blockDim.x + threadIdx.x;
    if (e < E) atomicAdd(&g_rowptr[dst[e] + 1], 1);
}

// single-block inclusive scan of g_rowptr[0..n]; also writes g_off
__global__ void scan_kernel(int n) {
    __shared__ int buf[1024];
    __shared__ int carry;
    if (threadIdx.x == 0) carry = 0;
    __syncthreads();
    for (int base = 0; base < n + 1; base += 1024) {
        int i = base + threadIdx.x;
        int v = (i < n + 1) ? g_rowptr[i] : 0;
        buf[threadIdx.x] = v;
        __syncthreads();
        for (int ofs = 1; ofs < 1024; ofs <<= 1) {
            int t = (threadIdx.x >= ofs) ? buf[threadIdx.x - ofs] : 0;
            __syncthreads();
            buf[threadIdx.x] += t;
            __syncthreads();
        }
        int inc = buf[threadIdx.x] + carry;
        if (i < n + 1) {
            g_rowptr[i] = inc;
            if (i < n) g_off[i] = inc;
        }
        __syncthreads();
        if (threadIdx.x == 1023) carry = inc;
        __syncthreads();
    }
}

__global__ void scatter_kernel(const int* __restrict__ src, const int* __restrict__ dst,
                               const float* __restrict__ w, int E) {
    int e = blockIdx.x * blockDim.x + threadIdx.x;
    if (e < E) {
        int p = atomicAdd(&g_off[dst[e]], 1);
        g_edge[p] = make_int2(src[e], __float_as_int(w[e]));
    }
}

// ---------------- graph convolutions (warp per node, CSR) ----------------
// writes t-major: g_gx[t*N*8 + node*8 + f]
__global__ void gconv_x(const float* __restrict__ x, int N) {
    int node = blockIdx.x * (blockDim.x >> 5) + (threadIdx.x >> 5);
    if (node >= N) return;
    int lane = threadIdx.x & 31;
    int s = g_rowptr[node], e = g_rowptr[node + 1];
    float a0 = 0.f, a1 = 0.f, a2 = 0.f;
    for (int i = s; i < e; i++) {
        int2 em = __ldg(&g_edge[i]);
        float w = __int_as_float(em.y);
        const float* f = x + (size_t)em.x * 96;
        a0 += w * __ldg(f + lane);
        a1 += w * __ldg(f + lane + 32);
        a2 += w * __ldg(f + lane + 64);
    }
    size_t N8 = (size_t)N * 8;
#pragma unroll
    for (int j = 0; j < 3; j++) {
        int v = lane + j * 32;
        float a = (j == 0) ? a0 : (j == 1) ? a1 : a2;
        g_gx[(size_t)(v % 12) * N8 + (size_t)node * 8 + (v / 12)] = a;
    }
}

// 64-col aggregation over fp16 table g_rh16 -> fp32 g_grh
__global__ void gconv64_h16(int N) {
    int node = blockIdx.x * (blockDim.x >> 5) + (threadIdx.x >> 5);
    if (node >= N) return;
    int lane = threadIdx.x & 31;
    int s = g_rowptr[node], e = g_rowptr[node + 1];
    float ax = 0.f, ay = 0.f;
    int i = s;
    for (; i + 3 < e; i += 4) {
        int2 e0 = __ldg(&g_edge[i]),     e1 = __ldg(&g_edge[i + 1]);
        int2 e2 = __ldg(&g_edge[i + 2]), e3 = __ldg(&g_edge[i + 3]);
        float2 f0 = __half22float2(__ldg(&g_rh16[(size_t)e0.x * 32 + lane]));
        float2 f1 = __half22float2(__ldg(&g_rh16[(size_t)e1.x * 32 + lane]));
        float2 f2 = __half22float2(__ldg(&g_rh16[(size_t)e2.x * 32 + lane]));
        float2 f3 = __half22float2(__ldg(&g_rh16[(size_t)e3.x * 32 + lane]));
        float w0 = __int_as_float(e0.y), w1 = __int_as_float(e1.y);
        float w2 = __int_as_float(e2.y), w3 = __int_as_float(e3.y);
        ax += w0 * f0.x; ay += w0 * f0.y;
        ax += w1 * f1.x; ay += w1 * f1.y;
        ax += w2 * f2.x; ay += w2 * f2.y;
        ax += w3 * f3.x; ay += w3 * f3.y;
    }
    for (; i < e; i++) {
        int2 e0 = __ldg(&g_edge[i]);
        float w0 = __int_as_float(e0.y);
        float2 f0 = __half22float2(__ldg(&g_rh16[(size_t)e0.x * 32 + lane]));
        ax += w0 * f0.x; ay += w0 * f0.y;
    }
    ((float2*)(g_grh + (size_t)node * 64))[lane] = make_float2(ax, ay);
}

// dual aggregation over packed fp16 {h0,h1} table -> fp32 gpair row of 128
__global__ void gconv_dual_h16(int N) {
    int node = blockIdx.x * (blockDim.x >> 5) + (threadIdx.x >> 5);
    if (node >= N) return;
    int lane = threadIdx.x & 31;
    int s = g_rowptr[node], e = g_rowptr[node + 1];
    float ax = 0.f, ay = 0.f, bx = 0.f, by = 0.f;
    int i = s;
    for (; i + 1 < e; i += 2) {
        int2 e0 = __ldg(&g_edge[i]), e1 = __ldg(&g_edge[i + 1]);
        uint2 p0 = __ldg(&g_hpk[(size_t)e0.x * 32 + lane]);
        uint2 p1 = __ldg(&g_hpk[(size_t)e1.x * 32 + lane]);
        float w0 = __int_as_float(e0.y), w1 = __int_as_float(e1.y);
        float2 a0 = __half22float2(*(__half2*)&p0.x), b0 = __half22float2(*(__half2*)&p0.y);
        float2 a1 = __half22float2(*(__half2*)&p1.x), b1 = __half22float2(*(__half2*)&p1.y);
        ax += w0 * a0.x; ay += w0 * a0.y; bx += w0 * b0.x; by += w0 * b0.y;
        ax += w1 * a1.x; ay += w1 * a1.y; bx += w1 * b1.x; by += w1 * b1.y;
    }
    if (i < e) {
        int2 e0 = __ldg(&g_edge[i]);
        uint2 p0 = __ldg(&g_hpk[(size_t)e0.x * 32 + lane]);
        float w0 = __int_as_float(e0.y);
        float2 a0 = __half22float2(*(__half2*)&p0.x), b0 = __half22float2(*(__half2*)&p0.y);
        ax += w0 * a0.x; ay += w0 * a0.y; bx += w0 * b0.x; by += w0 * b0.y;
    }
    ((float2*)(g_gpair + (size_t)node * 128))[lane]      = make_float2(ax, ay);
    ((float2*)(g_gpair + (size_t)node * 128 + 64))[lane] = make_float2(bx, by);
}

// ================= split-fp16 MMA GEMM helpers =================
// Block tile 64x64, 128 threads (4 warps as 2m x 2n, warp tile 32x32).
// A (64 x Kpad) and W^T (64 x Kpad) staged in smem as fp16 hi/lo pairs,
// row stride KS = Kpad + 8 halves (conflict-free for mma operand loads).
// D = Ahi@Whi + Ahi@Wlo + Alo@Whi  (fp32-accurate; lo*lo term ~2^-22 dropped)

__device__ __forceinline__ void stage_w(__half* SWh, __half* SWl,
                                        const float* __restrict__ W, int ldw,
                                        int K, int Kpad, int KS, int tid) {
    for (int idx = tid; idx < (Kpad << 6); idx += 128) {
        int k = idx >> 6, c = idx & 63;
        float v = (k < K) ? __ldg(&W[k * ldw + c]) : 0.f;
        __half hi = __float2half_rn(v);
        __half lo = __float2half_rn(v - __half2float(hi));
        SWh[c * KS + k] = hi;
        SWl[c * KS + k] = lo;
    }
}

__device__ __forceinline__ void stage_a(__half* SAh, __half* SAl,
                                        const float* __restrict__ A1, int lda1, int K1,
                                        const float* __restrict__ A2, int lda2, int K,
                                        int Kpad, int KS, int row0, int nrows, int tid) {
    int wid = tid >> 5, lane = tid & 31;
    for (int r = wid; r < 64; r += 4) {
        int grow = row0 + r;
        for (int k = lane; k < Kpad; k += 32) {
            float v = 0.f;
            if (grow < nrows && k < K)
                v = (k < K1) ? __ldg(&A1[(size_t)grow * lda1 + k])
                             : __ldg(&A2[(size_t)grow * lda2 + (k - K1)]);
            __half hi = __float2half_rn(v);
            __half lo = __float2half_rn(v - __half2float(hi));
            SAh[r * KS + k] = hi;
            SAl[r * KS + k] = lo;
        }
    }
}

// mainloop: fills acc[2][4][4]
#define MMA_MAINLOOP(SAh, SAl, SWh, SWl, Kpad, KS, mo, no, gid, tg, acc)            \
    for (int k0 = 0; k0 < (Kpad); k0 += 16) {                                       \
        unsigned ah[2][4], al[2][4];                                                \
        _Pragma("unroll")                                                           \
        for (int mf = 0; mf < 2; mf++) {                                            \
            int r = (mo) + mf * 16 + (gid);                                         \
            const __half* p0 = &(SAh)[r * (KS) + k0 + (tg) * 2];                    \
            const __half* p1 = &(SAh)[(r + 8) * (KS) + k0 + (tg) * 2];              \
            ah[mf][0] = *(const unsigned*)p0;                                       \
            ah[mf][1] = *(const unsigned*)p1;                                       \
            ah[mf][2] = *(const unsigned*)(p0 + 8);                                 \
            ah[mf][3] = *(const unsigned*)(p1 + 8);                                 \
            const __half* q0 = &(SAl)[r * (KS) + k0 + (tg) * 2];                    \
            const __half* q1 = &(SAl)[(r + 8) * (KS) + k0 + (tg) * 2];              \
            al[mf][0] = *(const unsigned*)q0;                                       \
            al[mf][1] = *(const unsigned*)q1;                                       \
            al[mf][2] = *(const unsigned*)(q0 + 8);                                 \
            al[mf][3] = *(const unsigned*)(q1 + 8);                                 \
        }                                                                           \
        _Pragma("unroll")                                                           \
        for (int nf = 0; nf < 4; nf++) {                                            \
            int n = (no) + nf * 8 + (gid);                                          \
            const __half* bph = &(SWh)[n * (KS) + k0 + (tg) * 2];                   \
            const __half* bpl = &(SWl)[n * (KS) + k0 + (tg) * 2];                   \
            unsigned bh0 = *(const unsigned*)bph, bh1 = *(const unsigned*)(bph + 8);\
            unsigned bl0 = *(const unsigned*)bpl, bl1 = *(const unsigned*)(bpl + 8);\
            _Pragma("unroll")                                                       \
            for (int mf = 0; mf < 2; mf++) {                                        \
                MMA16816(acc[mf][nf], ah[mf], bh0, bh1);                            \
                MMA16816(acc[mf][nf], ah[mf], bl0, bl1);                            \
                MMA16816(acc[mf][nf], al[mf], bh0, bh1);                            \
            }                                                                       \
        }                                                                           \
    }

// ============ gate GEMM (MMA): rz = sigmoid([A1|A2] @ W + b) ============
// grid.y: cy=0 -> cols 0..63 -> rh16 = sig*h (fp16); cy=1 -> cols 64..127 -> z (fp32)
__global__ void __launch_bounds__(128) gate_mma(
        const float* __restrict__ A1, int lda1, int K1,
        const float* __restrict__ A2, int lda2, int K2, int Kpad,
        const float* __restrict__ W, const float* __restrict__ bias,
        const float* __restrict__ h,
        float* __restrict__ z, int nrows) {
    extern __shared__ __align__(16) char smraw[];
    const int K = K1 + K2, KS = Kpad + 8;
    __half* SAh = (__half*)smraw;
    __half* SAl = SAh + 64 * KS;
    __half* SWh = SAl + 64 * KS;
    __half* SWl = SWh + 64 * KS;
    int tid = threadIdx.x;
    int cy = blockIdx.y;
    int row0 = blockIdx.x * 64;

    stage_w(SWh, SWl, W + cy * 64, 128, K, Kpad, KS, tid);
    stage_a(SAh, SAl, A1, lda1, K1, A2, lda2, K, Kpad, KS, row0, nrows, tid);
    __syncthreads();

    int lane = tid & 31, warp = tid >> 5;
    int gid = lane >> 2, tg = lane & 3;
    int mo = (warp & 1) * 32, no = (warp >> 1) * 32;
    float acc[2][4][4];
#pragma unroll
    for (int mf = 0; mf < 2; mf++)
#pragma unroll
        for (int nf = 0; nf < 4; nf++)
#pragma unroll
            for (int q = 0; q < 4; q++) acc[mf][nf][q] = 0.f;

    MMA_MAINLOOP(SAh, SAl, SWh, SWl, Kpad, KS, mo, no, gid, tg, acc)

#pragma unroll
    for (int mf = 0; mf < 2; mf++) {
#pragma unroll
        for (int nf = 0; nf < 4; nf++) {
            int j = no + nf * 8 + tg * 2;
            float b0 = __ldg(&bias[cy * 64 + j]);
            float b1 = __ldg(&bias[cy * 64 + j + 1]);
#pragma unroll
            for (int rr = 0; rr < 2; rr++) {
                int grow = row0 + mo + mf * 16 + gid + rr * 8;
                if (grow >= nrows) continue;
                float v0 = sigmoid_fast(acc[mf][nf][rr * 2 + 0] + b0);
                float v1 = sigmoid_fast(acc[mf][nf][rr * 2 + 1] + b1);
                if (cy == 0) {
                    float2 h2 = *(const float2*)&h[(size_t)grow * 64 + j];
                    g_rh16[(size_t)grow * 32 + (j >> 1)] =
                        __floats2half2_rn(v0 * h2.x, v1 * h2.y);
                } else {
                    *(float2*)&z[(size_t)grow * 64 + j] = make_float2(v0, v1);
                }
            }
        }
    }
}

// ============ cand GEMM (MMA): c = tanh([A1|A2] @ W + b); h = z*h + (1-z)*c ============
__global__ void __launch_bounds__(128) cand_mma(
        const float* __restrict__ A1, int lda1, int K1,
        const float* __restrict__ A2, int lda2, int K2, int Kpad,
        const float* __restrict__ W, const float* __restrict__ bias,
        const float* __restrict__ z,
        float* __restrict__ h, int slot, int nrows) {
    extern __shared__ __align__(16) char smraw[];
    const int K = K1 + K2, KS = Kpad + 8;
    __half* SAh = (__half*)smraw;
    __half* SAl = SAh + 64 * KS;
    __half* SWh = SAl + 64 * KS;
    __half* SWl = SWh + 64 * KS;
    int tid = threadIdx.x;
    int row0 = blockIdx.x * 64;

    stage_w(SWh, SWl, W, 64, K, Kpad, KS, tid);
    stage_a(SAh, SAl, A1, lda1, K1, A2, lda2, K, Kpad, KS, row0, nrows, tid);
    __syncthreads();

    int lane = tid & 31, warp = tid >> 5;
    int gid = lane >> 2, tg = lane & 3;
    int mo = (warp & 1) * 32, no = (warp >> 1) * 32;
    float acc[2][4][4];
#pragma unroll
    for (int mf = 0; mf < 2; mf++)
#pragma unroll
        for (int nf = 0; nf < 4; nf++)
#pragma unroll
            for (int q = 0; q < 4; q++) acc[mf][nf][q] = 0.f;

    MMA_MAINLOOP(SAh, SAl, SWh, SWl, Kpad, KS, mo, no, gid, tg, acc)

#pragma unroll
    for (int mf = 0; mf < 2; mf++) {
#pragma unroll
        for (int nf = 0; nf < 4; nf++) {
            int j = no + nf * 8 + tg * 2;
            float b0 = __ldg(&bias[j]);
            float b1 = __ldg(&bias[j + 1]);
#pragma unroll
            for (int rr = 0; rr < 2; rr++) {
                int grow = row0 + mo + mf * 16 + gid + rr * 8;
                if (grow >= nrows) continue;
                float c0 = tanh_fast(acc[mf][nf][rr * 2 + 0] + b0);
                float c1 = tanh_fast(acc[mf][nf][rr * 2 + 1] + b1);
                float2 z2 = *(const float2*)&z[(size_t)grow * 64 + j];
                float2 h2 = *(const float2*)&h[(size_t)grow * 64 + j];
                float n0 = z2.x * h2.x + (1.f - z2.x) * c0;
                float n1 = z2.y * h2.y + (1.f - z2.y) * c1;
                *(float2*)&h[(size_t)grow * 64 + j] = make_float2(n0, n1);
                __half2 q = __floats2half2_rn(n0, n1);
                unsigned* hp = (unsigned*)&g_hpk[(size_t)grow * 32 + (j >> 1)];
                hp[slot] = *(unsigned*)&q;
            }
        }
    }
}

// ---------------- output: out = h1 @ Wout + bout (Wout is 64x1) ----------------
__global__ void out_kernel(const float* __restrict__ h1, const float* __restrict__ Wout,
                           const float* __restrict__ bout, float* __restrict__ out, int N) {
    int node = blockIdx.x * (blockDim.x >> 5) + (threadIdx.x >> 5);
    if (node >= N) return;
    int lane = threadIdx.x & 31;
    float v = h1[(size_t)node * 64 + lane] * __ldg(&Wout[lane]) +
              h1[(size_t)node * 64 + lane + 32] * __ldg(&Wout[lane + 32]);
#pragma unroll
    for (int o = 16; o > 0; o >>= 1) v += __shfl_xor_sync(0xffffffffu, v, o);
    if (lane == 0) out[node] = v + bout[0];
}

// ---------------- cleanup: restore zero-state invariant for the next call ----------
__global__ void cleanup_kernel(int N) {
    int stride = gridDim.x * blockDim.x;
    float2 zz = make_float2(0.f, 0.f);
    for (int i = blockIdx.x * blockDim.x + threadIdx.x; i < N * 64; i += stride) {
        ((float2*)g_gpair)[i] = zz;           // N*128 floats
        if (i < N * 32) {
            ((float2*)g_h0)[i] = zz;          // N*64 floats
            ((float2*)g_h1)[i] = zz;
            g_hpk[i] = make_uint2(0u, 0u);    // N*32 uint2
        }
        if (i < N + 1) g_rowptr[i] = 0;
    }
}

// ---------------- launch ----------------
extern "C" void kernel_launch(void* const* d_in, const int* in_sizes, int n_in,
                              void* d_out, int out_size) {
    const float* x   = (const float*)d_in[0];
    const int*   ei  = (const int*)d_in[1];
    const float* ew  = (const float*)d_in[2];
    const float* Wg0 = (const float*)d_in[3];
    const float* bg0 = (const float*)d_in[4];
    const float* Wc0 = (const float*)d_in[5];
    const float* bc0 = (const float*)d_in[6];
    const float* Wg1 = (const float*)d_in[7];
    const float* bg1 = (const float*)d_in[8];
    const float* Wc1 = (const float*)d_in[9];
    const float* bc1 = (const float*)d_in[10];
    const float* Wout = (const float*)d_in[11];
    const float* bout = (const float*)d_in[12];

    int N = in_sizes[0] / 96;   // F=8, T=12
    int E = in_sizes[2];
    if (N > NMAX || E > EMAX) return;
    const int* src = ei;
    const int* dst = ei + E;

    float *p_gx, *p_h0, *p_h1, *p_gpair, *p_grh, *p_z;
    cudaGetSymbolAddress((void**)&p_gx, g_gx);
    cudaGetSymbolAddress((void**)&p_h0, g_h0);
    cudaGetSymbolAddress((void**)&p_h1, g_h1);
    cudaGetSymbolAddress((void**)&p_gpair, g_gpair);
    cudaGetSymbolAddress((void**)&p_grh, g_grh);
    cudaGetSymbolAddress((void**)&p_z, g_z);

    // smem: 4 tables of 64 rows x (Kpad+8) halves
    // Kpad=80  -> KS=88  -> 45056 B ; Kpad=128 -> KS=136 -> 69632 B
    cudaFuncSetAttribute(gate_mma, cudaFuncAttributeMaxDynamicSharedMemorySize, 71680);
    cudaFuncSetAttribute(cand_mma, cudaFuncAttributeMaxDynamicSharedMemorySize, 71680);
    size_t sm80  = (size_t)4 * 64 * 88  * 2;   // 45056
    size_t sm128 = (size_t)4 * 64 * 136 * 2;   // 69632

    // CSR build (rowptr enters zeroed; cleanup_kernel restores that at the end)
    hist_kernel<<<(E + 255) / 256, 256>>>(dst, E);              // 0
    scan_kernel<<<1, 1024>>>(N);                                // 1
    scatter_kernel<<<(E + 255) / 256, 256>>>(src, dst, ew, E);  // 2

    int gblocks = (N + 7) / 8;
    gconv_x<<<gblocks, 256>>>(x, N);                            // 3 (ncu-profiled slot)

    size_t N8 = (size_t)N * 8;
    int rb = (N + 63) / 64;
    dim3 gate_grid(rb, 2);

    for (int t = 0; t < 12; t++) {
        // ---- cell 0 ----  (gconv(h0_{t-1}) lives in gpair[:, 0:64] from prior dual pass)
        gate_mma<<<gate_grid, 128, sm80>>>(p_gx + (size_t)t * N8, 8, 8,
                                           p_gpair, 128, 64, 80,
                                           Wg0, bg0, p_h0, p_z, N);
        gconv64_h16<<<gblocks, 256>>>(N);
        cand_mma<<<rb, 128, sm80>>>(p_gx + (size_t)t * N8, 8, 8,
                                    p_grh, 64, 64, 80,
                                    Wc0, bc0, p_z, p_h0, 0, N);  // h0 <- new h0
        // ---- cell 1 ----
        gconv_dual_h16<<<gblocks, 256>>>(N);  // [gconv(h0_new) | gconv(h1)] from packed fp16
        gate_mma<<<gate_grid, 128, sm128>>>(p_gpair, 128, 128,
                                            p_grh, 64, 0, 128,
                                            Wg1, bg1, p_h1, p_z, N);
        gconv64_h16<<<gblocks, 256>>>(N);
        cand_mma<<<rb, 128, sm128>>>(p_gpair, 128, 64,
                                     p_grh, 64, 64, 128,
                                     Wc1, bc1, p_z, p_h1, 1, N);  // h1 <- new h1
    }

    out_kernel<<<gblocks, 256>>>(p_h1, Wout, bout, (float*)d_out, N);
    cleanup_kernel<<<512, 256>>>(N);
}

// round 14
// speedup vs baseline: 1.3842x; 1.3842x over previous
#include <cuda_runtime.h>
#include <cuda_fp16.h>
#include <math.h>

#define NMAX 50000
#define EMAX 800000

__device__ __forceinline__ float tanh_fast(float x) {
    float y;
    asm("tanh.approx.f32 %0, %1;" : "=f"(y) : "f"(x));
    return y;
}
__device__ __forceinline__ float sigmoid_fast(float x) {
    return 0.5f * tanh_fast(0.5f * x) + 0.5f;
}

#define MMA16816(d, a, b0_, b1_) \
    asm volatile("mma.sync.aligned.m16n8k16.row.col.f32.f16.f16.f32 " \
        "{%0,%1,%2,%3}, {%4,%5,%6,%7}, {%8,%9}, {%0,%1,%2,%3};" \
        : "+f"((d)[0]), "+f"((d)[1]), "+f"((d)[2]), "+f"((d)[3]) \
        : "r"((a)[0]), "r"((a)[1]), "r"((a)[2]), "r"((a)[3]), "r"(b0_), "r"(b1_))

// ---------------- scratch (device globals; zero-initialized at module load) ----------
__device__ __align__(16) unsigned g_gx16[NMAX * 96];    // gconv(x) hi/lo fp16, t-major:
                                                        // uint idx = t*N*8 + node*8 + q (q<4 hi, q>=4 lo)
__device__ __align__(16) float    g_h0[NMAX * 64];
__device__ __align__(16) float    g_h1[NMAX * 64];
__device__ __align__(16) unsigned g_gpair16[NMAX * 128]; // [gconv(h0)|gconv(h1)] hi(64u) lo(64u) per node
__device__ __align__(16) unsigned g_grh16[NMAX * 64];    // gconv(r*h): hi(32u) lo(32u) per node
__device__ __align__(16) float    g_z[NMAX * 64];
__device__ __align__(8)  __half2  g_rh16[NMAX * 32];     // r*h fp16 (gconv64 input)
__device__ __align__(16) uint2    g_hpk[NMAX * 32];      // packed {h0 half2, h1 half2} per lane
__device__ __align__(16) __half   g_w16[90112];          // pre-split, pre-transposed weights
__device__ int  g_rowptr[NMAX + 1];
__device__ int  g_off[NMAX];
__device__ __align__(8) int2 g_edge[EMAX];               // (src, w bits)

// weight table offsets (halves); layout per matrix: hi block [col][KS], then lo block
#define KS80  88
#define KS128 136
#define WG0H 0
#define WG0L (WG0H + 128 * KS80)    // 11264
#define WC0H (WG0L + 128 * KS80)    // 22528
#define WC0L (WC0H + 64 * KS80)     // 28160
#define WG1H (WC0L + 64 * KS80)     // 33792
#define WG1L (WG1H + 128 * KS128)   // 51200
#define WC1H (WG1L + 128 * KS128)   // 68608
#define WC1L (WC1H + 64 * KS128)    // 77312  (end 86016)

// NOTE: h0/h1/gpair16/hpk/rowptr must be zero at entry. Zero-initialized at module
// load; cleanup_kernel (last launch) re-zeroes them.

__global__ void hist_kernel(const int* __restrict__ dst, int E) {
    int e = blockIdx.x * blockDim.x + threadIdx.x;
    if (e < E) atomicAdd(&g_rowptr[dst[e] + 1], 1);
}

__global__ void scan_kernel(int n) {
    __shared__ int buf[1024];
    __shared__ int carry;
    if (threadIdx.x == 0) carry = 0;
    __syncthreads();
    for (int base = 0; base < n + 1; base += 1024) {
        int i = base + threadIdx.x;
        int v = (i < n + 1) ? g_rowptr[i] : 0;
        buf[threadIdx.x] = v;
        __syncthreads();
        for (int ofs = 1; ofs < 1024; ofs <<= 1) {
            int t = (threadIdx.x >= ofs) ? buf[threadIdx.x - ofs] : 0;
            __syncthreads();
            buf[threadIdx.x] += t;
            __syncthreads();
        }
        int inc = buf[threadIdx.x] + carry;
        if (i < n + 1) {
            g_rowptr[i] = inc;
            if (i < n) g_off[i] = inc;
        }
        __syncthreads();
        if (threadIdx.x == 1023) carry = inc;
        __syncthreads();
    }
}

__global__ void scatter_kernel(const int* __restrict__ src, const int* __restrict__ dst,
                               const float* __restrict__ w, int E) {
    int e = blockIdx.x * blockDim.x + threadIdx.x;
    if (e < E) {
        int p = atomicAdd(&g_off[dst[e]], 1);
        g_edge[p] = make_int2(src[e], __float_as_int(w[e]));
    }
}

// ---------------- weight prep: split fp32 -> (hi, lo) fp16, transposed [col][KS] ------
__global__ void prep_w(const float* __restrict__ W, int ldw, int K, int ncols, int KS,
                       int hi_off, int lo_off) {
    int idx = blockIdx.x * blockDim.x + threadIdx.x;
    if (idx >= ncols * KS) return;
    int col = idx / KS, k = idx - col * KS;
    float v = (k < K) ? __ldg(&W[k * ldw + col]) : 0.f;
    __half hi = __float2half_rn(v);
    __half lo = __float2half_rn(v - __half2float(hi));
    g_w16[hi_off + col * KS + k] = hi;
    g_w16[lo_off + col * KS + k] = lo;
}

// ---------------- graph convolutions (warp per node, CSR) ----------------
// emits hi/lo fp16 t-major table
__global__ void gconv_x(const float* __restrict__ x, int N) {
    int node = blockIdx.x * (blockDim.x >> 5) + (threadIdx.x >> 5);
    if (node >= N) return;
    int lane = threadIdx.x & 31;
    int s = g_rowptr[node], e = g_rowptr[node + 1];
    float a0 = 0.f, a1 = 0.f, a2 = 0.f;
    for (int i = s; i < e; i++) {
        int2 em = __ldg(&g_edge[i]);
        float w = __int_as_float(em.y);
        const float* f = x + (size_t)em.x * 96;
        a0 += w * __ldg(f + lane);
        a1 += w * __ldg(f + lane + 32);
        a2 += w * __ldg(f + lane + 64);
    }
    __half* gx = (__half*)g_gx16;
    size_t N16 = (size_t)N * 16;
#pragma unroll
    for (int j = 0; j < 3; j++) {
        int v = lane + j * 32;
        float a = (j == 0) ? a0 : (j == 1) ? a1 : a2;
        __half hi = __float2half_rn(a);
        __half lo = __float2half_rn(a - __half2float(hi));
        size_t base = (size_t)(v % 12) * N16 + (size_t)node * 16 + (v / 12);
        gx[base]     = hi;
        gx[base + 8] = lo;
    }
}

// 64-col aggregation over fp16 table g_rh16 -> hi/lo fp16 g_grh16
__global__ void gconv64_h16(int N) {
    int node = blockIdx.x * (blockDim.x >> 5) + (threadIdx.x >> 5);
    if (node >= N) return;
    int lane = threadIdx.x & 31;
    int s = g_rowptr[node], e = g_rowptr[node + 1];
    float ax = 0.f, ay = 0.f;
    int i = s;
    for (; i + 3 < e; i += 4) {
        int2 e0 = __ldg(&g_edge[i]),     e1 = __ldg(&g_edge[i + 1]);
        int2 e2 = __ldg(&g_edge[i + 2]), e3 = __ldg(&g_edge[i + 3]);
        float2 f0 = __half22float2(__ldg(&g_rh16[(size_t)e0.x * 32 + lane]));
        float2 f1 = __half22float2(__ldg(&g_rh16[(size_t)e1.x * 32 + lane]));
        float2 f2 = __half22float2(__ldg(&g_rh16[(size_t)e2.x * 32 + lane]));
        float2 f3 = __half22float2(__ldg(&g_rh16[(size_t)e3.x * 32 + lane]));
        float w0 = __int_as_float(e0.y), w1 = __int_as_float(e1.y);
        float w2 = __int_as_float(e2.y), w3 = __int_as_float(e3.y);
        ax += w0 * f0.x; ay += w0 * f0.y;
        ax += w1 * f1.x; ay += w1 * f1.y;
        ax += w2 * f2.x; ay += w2 * f2.y;
        ax += w3 * f3.x; ay += w3 * f3.y;
    }
    for (; i < e; i++) {
        int2 e0 = __ldg(&g_edge[i]);
        float w0 = __int_as_float(e0.y);
        float2 f0 = __half22float2(__ldg(&g_rh16[(size_t)e0.x * 32 + lane]));
        ax += w0 * f0.x; ay += w0 * f0.y;
    }
    __half2 hi = __floats2half2_rn(ax, ay);
    float2 hf = __half22float2(hi);
    __half2 lo = __floats2half2_rn(ax - hf.x, ay - hf.y);
    g_grh16[(size_t)node * 64 + lane]      = *(unsigned*)&hi;
    g_grh16[(size_t)node * 64 + 32 + lane] = *(unsigned*)&lo;
}

// dual aggregation over packed fp16 {h0,h1} table -> hi/lo fp16 gpair row
__global__ void gconv_dual_h16(int N) {
    int node = blockIdx.x * (blockDim.x >> 5) + (threadIdx.x >> 5);
    if (node >= N) return;
    int lane = threadIdx.x & 31;
    int s = g_rowptr[node], e = g_rowptr[node + 1];
    float ax = 0.f, ay = 0.f, bx = 0.f, by = 0.f;
    int i = s;
    for (; i + 1 < e; i += 2) {
        int2 e0 = __ldg(&g_edge[i]), e1 = __ldg(&g_edge[i + 1]);
        uint2 p0 = __ldg(&g_hpk[(size_t)e0.x * 32 + lane]);
        uint2 p1 = __ldg(&g_hpk[(size_t)e1.x * 32 + lane]);
        float w0 = __int_as_float(e0.y), w1 = __int_as_float(e1.y);
        float2 a0 = __half22float2(*(__half2*)&p0.x), b0 = __half22float2(*(__half2*)&p0.y);
        float2 a1 = __half22float2(*(__half2*)&p1.x), b1 = __half22float2(*(__half2*)&p1.y);
        ax += w0 * a0.x; ay += w0 * a0.y; bx += w0 * b0.x; by += w0 * b0.y;
        ax += w1 * a1.x; ay += w1 * a1.y; bx += w1 * b1.x; by += w1 * b1.y;
    }
    if (i < e) {
        int2 e0 = __ldg(&g_edge[i]);
        uint2 p0 = __ldg(&g_hpk[(size_t)e0.x * 32 + lane]);
        float w0 = __int_as_float(e0.y);
        float2 a0 = __half22float2(*(__half2*)&p0.x), b0 = __half22float2(*(__half2*)&p0.y);
        ax += w0 * a0.x; ay += w0 * a0.y; bx += w0 * b0.x; by += w0 * b0.y;
    }
    size_t base = (size_t)node * 128;
    __half2 ahi = __floats2half2_rn(ax, ay);
    float2 af = __half22float2(ahi);
    __half2 alo = __floats2half2_rn(ax - af.x, ay - af.y);
    __half2 bhi = __floats2half2_rn(bx, by);
    float2 bf = __half22float2(bhi);
    __half2 blo = __floats2half2_rn(bx - bf.x, by - bf.y);
    g_gpair16[base + lane]      = *(unsigned*)&ahi;
    g_gpair16[base + 32 + lane] = *(unsigned*)&bhi;
    g_gpair16[base + 64 + lane] = *(unsigned*)&alo;
    g_gpair16[base + 96 + lane] = *(unsigned*)&blo;
}

// ================= split-fp16 MMA GEMM =================
// Block 64x64, 128 threads (4 warps 2m x 2n, warp tile 32x32).
// A staged from pre-split fp16 uint tables; W copied from pre-split pre-transposed table.
// D = Ahi@Whi + Ahi@Wlo + Alo@Whi (fp32-accurate).

__device__ __forceinline__ void stage_a16(unsigned* SAh_u, unsigned* SAl_u,
        const unsigned* __restrict__ A1u, int s1, int lo1, int n1,
        const unsigned* __restrict__ A2u, int s2, int lo2, int n2,
        int KSu, int row0, int nrows, int tid) {
    int warp = tid >> 5, lane = tid & 31;
    for (int r = warp; r < 64; r += 4) {
        int grow = row0 + r;
        const unsigned* a1 = A1u + (size_t)grow * s1;
        const unsigned* a2 = A2u + (size_t)grow * s2;
        bool ok = grow < nrows;
        for (int k2 = lane; k2 < KSu; k2 += 32) {
            unsigned vh = 0u, vl = 0u;
            if (ok) {
                if (k2 < n1)           { vh = __ldg(a1 + k2);       vl = __ldg(a1 + lo1 + k2); }
                else if (k2 < n1 + n2) { int j = k2 - n1;
                                         vh = __ldg(a2 + j);        vl = __ldg(a2 + lo2 + j); }
            }
            SAh_u[r * KSu + k2] = vh;
            SAl_u[r * KSu + k2] = vl;
        }
    }
}

__device__ __forceinline__ void stage_w16(unsigned* SWh_u, unsigned* SWl_u,
                                          int hi_off, int lo_off, int KS, int tid) {
    const uint4* srch = (const uint4*)(g_w16 + hi_off);
    const uint4* srcl = (const uint4*)(g_w16 + lo_off);
    uint4* dsth = (uint4*)SWh_u;
    uint4* dstl = (uint4*)SWl_u;
    int n4 = (64 * KS) >> 3;   // halves -> uint4
    for (int i = tid; i < n4; i += 128) {
        dsth[i] = __ldg(&srch[i]);
        dstl[i] = __ldg(&srcl[i]);
    }
}

#define MMA_MAINLOOP(SAh, SAl, SWh, SWl, Kpad, KS, mo, no, gid, tg, acc)            \
    for (int k0 = 0; k0 < (Kpad); k0 += 16) {                                       \
        unsigned ah[2][4], al[2][4];                                                \
        _Pragma("unroll")                                                           \
        for (int mf = 0; mf < 2; mf++) {                                            \
            int r = (mo) + mf * 16 + (gid);                                         \
            const __half* p0 = &(SAh)[r * (KS) + k0 + (tg) * 2];                    \
            const __half* p1 = &(SAh)[(r + 8) * (KS) + k0 + (tg) * 2];              \
            ah[mf][0] = *(const unsigned*)p0;                                       \
            ah[mf][1] = *(const unsigned*)p1;                                       \
            ah[mf][2] = *(const unsigned*)(p0 + 8);                                 \
            ah[mf][3] = *(const unsigned*)(p1 + 8);                                 \
            const __half* q0 = &(SAl)[r * (KS) + k0 + (tg) * 2];                    \
            const __half* q1 = &(SAl)[(r + 8) * (KS) + k0 + (tg) * 2];              \
            al[mf][0] = *(const unsigned*)q0;                                       \
            al[mf][1] = *(const unsigned*)q1;                                       \
            al[mf][2] = *(const unsigned*)(q0 + 8);                                 \
            al[mf][3] = *(const unsigned*)(q1 + 8);                                 \
        }                                                                           \
        _Pragma("unroll")                                                           \
        for (int nf = 0; nf < 4; nf++) {                                            \
            int n = (no) + nf * 8 + (gid);                                          \
            const __half* bph = &(SWh)[n * (KS) + k0 + (tg) * 2];                   \
            const __half* bpl = &(SWl)[n * (KS) + k0 + (tg) * 2];                   \
            unsigned bh0 = *(const unsigned*)bph, bh1 = *(const unsigned*)(bph + 8);\
            unsigned bl0 = *(const unsigned*)bpl, bl1 = *(const unsigned*)(bpl + 8);\
            _Pragma("unroll")                                                       \
            for (int mf = 0; mf < 2; mf++) {                                        \
                MMA16816(acc[mf][nf], ah[mf], bh0, bh1);                            \
                MMA16816(acc[mf][nf], ah[mf], bl0, bl1);                            \
                MMA16816(acc[mf][nf], al[mf], bh0, bh1);                            \
            }                                                                       \
        }                                                                           \
    }

// gate: rz = sigmoid(A @ W + b); cy=0 -> rh16 = sig*h; cy=1 -> z
__global__ void __launch_bounds__(128) gate_mma(
        const unsigned* __restrict__ A1u, int s1, int lo1, int n1,
        const unsigned* __restrict__ A2u, int s2, int lo2, int n2,
        int Kpad, int w_hi, int w_lo,
        const float* __restrict__ bias, const float* __restrict__ h,
        float* __restrict__ z, int nrows) {
    extern __shared__ __align__(16) char smraw[];
    const int KS = Kpad + 8, KSu = KS >> 1;
    __half* SAh = (__half*)smraw;
    __half* SAl = SAh + 64 * KS;
    __half* SWh = SAl + 64 * KS;
    __half* SWl = SWh + 64 * KS;
    int tid = threadIdx.x;
    int cy = blockIdx.y;
    int row0 = blockIdx.x * 64;

    stage_w16((unsigned*)SWh, (unsigned*)SWl, w_hi + cy * 64 * KS, w_lo + cy * 64 * KS, KS, tid);
    stage_a16((unsigned*)SAh, (unsigned*)SAl, A1u, s1, lo1, n1, A2u, s2, lo2, n2,
              KSu, row0, nrows, tid);
    __syncthreads();

    int lane = tid & 31, warp = tid >> 5;
    int gid = lane >> 2, tg = lane & 3;
    int mo = (warp & 1) * 32, no = (warp >> 1) * 32;
    float acc[2][4][4];
#pragma unroll
    for (int mf = 0; mf < 2; mf++)
#pragma unroll
        for (int nf = 0; nf < 4; nf++)
#pragma unroll
            for (int q = 0; q < 4; q++) acc[mf][nf][q] = 0.f;

    MMA_MAINLOOP(SAh, SAl, SWh, SWl, Kpad, KS, mo, no, gid, tg, acc)

#pragma unroll
    for (int mf = 0; mf < 2; mf++) {
#pragma unroll
        for (int nf = 0; nf < 4; nf++) {
            int j = no + nf * 8 + tg * 2;
            float b0 = __ldg(&bias[cy * 64 + j]);
            float b1 = __ldg(&bias[cy * 64 + j + 1]);
#pragma unroll
            for (int rr = 0; rr < 2; rr++) {
                int grow = row0 + mo + mf * 16 + gid + rr * 8;
                if (grow >= nrows) continue;
                float v0 = sigmoid_fast(acc[mf][nf][rr * 2 + 0] + b0);
                float v1 = sigmoid_fast(acc[mf][nf][rr * 2 + 1] + b1);
                if (cy == 0) {
                    float2 h2 = *(const float2*)&h[(size_t)grow * 64 + j];
                    g_rh16[(size_t)grow * 32 + (j >> 1)] =
                        __floats2half2_rn(v0 * h2.x, v1 * h2.y);
                } else {
                    *(float2*)&z[(size_t)grow * 64 + j] = make_float2(v0, v1);
                }
            }
        }
    }
}

// cand: c = tanh(A @ W + b); h = z*h + (1-z)*c; fp16 copy into hpk slot
__global__ void __launch_bounds__(128) cand_mma(
        const unsigned* __restrict__ A1u, int s1, int lo1, int n1,
        const unsigned* __restrict__ A2u, int s2, int lo2, int n2,
        int Kpad, int w_hi, int w_lo,
        const float* __restrict__ bias, const float* __restrict__ z,
        float* __restrict__ h, int slot, int nrows) {
    extern __shared__ __align__(16) char smraw[];
    const int KS = Kpad + 8, KSu = KS >> 1;
    __half* SAh = (__half*)smraw;
    __half* SAl = SAh + 64 * KS;
    __half* SWh = SAl + 64 * KS;
    __half* SWl = SWh + 64 * KS;
    int tid = threadIdx.x;
    int row0 = blockIdx.x * 64;

    stage_w16((unsigned*)SWh, (unsigned*)SWl, w_hi, w_lo, KS, tid);
    stage_a16((unsigned*)SAh, (unsigned*)SAl, A1u, s1, lo1, n1, A2u, s2, lo2, n2,
              KSu, row0, nrows, tid);
    __syncthreads();

    int lane = tid & 31, warp = tid >> 5;
    int gid = lane >> 2, tg = lane & 3;
    int mo = (warp & 1) * 32, no = (warp >> 1) * 32;
    float acc[2][4][4];
#pragma unroll
    for (int mf = 0; mf < 2; mf++)
#pragma unroll
        for (int nf = 0; nf < 4; nf++)
#pragma unroll
            for (int q = 0; q < 4; q++) acc[mf][nf][q] = 0.f;

    MMA_MAINLOOP(SAh, SAl, SWh, SWl, Kpad, KS, mo, no, gid, tg, acc)

#pragma unroll
    for (int mf = 0; mf < 2; mf++) {
#pragma unroll
        for (int nf = 0; nf < 4; nf++) {
            int j = no + nf * 8 + tg * 2;
            float b0 = __ldg(&bias[j]);
            float b1 = __ldg(&bias[j + 1]);
#pragma unroll
            for (int rr = 0; rr < 2; rr++) {
                int grow = row0 + mo + mf * 16 + gid + rr * 8;
                if (grow >= nrows) continue;
                float c0 = tanh_fast(acc[mf][nf][rr * 2 + 0] + b0);
                float c1 = tanh_fast(acc[mf][nf][rr * 2 + 1] + b1);
                float2 z2 = *(const float2*)&z[(size_t)grow * 64 + j];
                float2 h2 = *(const float2*)&h[(size_t)grow * 64 + j];
                float n0 = z2.x * h2.x + (1.f - z2.x) * c0;
                float n1 = z2.y * h2.y + (1.f - z2.y) * c1;
                *(float2*)&h[(size_t)grow * 64 + j] = make_float2(n0, n1);
                __half2 q = __floats2half2_rn(n0, n1);
                unsigned* hp = (unsigned*)&g_hpk[(size_t)grow * 32 + (j >> 1)];
                hp[slot] = *(unsigned*)&q;
            }
        }
    }
}

// ---------------- output: out = h1 @ Wout + bout ----------------
__global__ void out_kernel(const float* __restrict__ h1, const float* __restrict__ Wout,
                           const float* __restrict__ bout, float* __restrict__ out, int N) {
    int node = blockIdx.x * (blockDim.x >> 5) + (threadIdx.x >> 5);
    if (node >= N) return;
    int lane = threadIdx.x & 31;
    float v = h1[(size_t)node * 64 + lane] * __ldg(&Wout[lane]) +
              h1[(size_t)node * 64 + lane + 32] * __ldg(&Wout[lane + 32]);
#pragma unroll
    for (int o = 16; o > 0; o >>= 1) v += __shfl_xor_sync(0xffffffffu, v, o);
    if (lane == 0) out[node] = v + bout[0];
}

// ---------------- cleanup: restore zero-state invariant ----------------
__global__ void cleanup_kernel(int N) {
    int stride = gridDim.x * blockDim.x;
    for (int i = blockIdx.x * blockDim.x + threadIdx.x; i < N * 128; i += stride) {
        g_gpair16[i] = 0u;
        if (i < N * 64) { g_h0[i] = 0.f; g_h1[i] = 0.f; }
        if (i < N * 32) g_hpk[i] = make_uint2(0u, 0u);
        if (i < N + 1) g_rowptr[i] = 0;
    }
}

// ---------------- launch ----------------
extern "C" void kernel_launch(void* const* d_in, const int* in_sizes, int n_in,
                              void* d_out, int out_size) {
    const float* x   = (const float*)d_in[0];
    const int*   ei  = (const int*)d_in[1];
    const float* ew  = (const float*)d_in[2];
    const float* Wg0 = (const float*)d_in[3];
    const float* bg0 = (const float*)d_in[4];
    const float* Wc0 = (const float*)d_in[5];
    const float* bc0 = (const float*)d_in[6];
    const float* Wg1 = (const float*)d_in[7];
    const float* bg1 = (const float*)d_in[8];
    const float* Wc1 = (const float*)d_in[9];
    const float* bc1 = (const float*)d_in[10];
    const float* Wout = (const float*)d_in[11];
    const float* bout = (const float*)d_in[12];

    int N = in_sizes[0] / 96;   // F=8, T=12
    int E = in_sizes[2];
    if (N > NMAX || E > EMAX) return;
    const int* src = ei;
    const int* dst = ei + E;

    unsigned *p_gx16, *p_gpair16, *p_grh16;
    float *p_h0, *p_h1, *p_z;
    cudaGetSymbolAddress((void**)&p_gx16, g_gx16);
    cudaGetSymbolAddress((void**)&p_h0, g_h0);
    cudaGetSymbolAddress((void**)&p_h1, g_h1);
    cudaGetSymbolAddress((void**)&p_gpair16, g_gpair16);
    cudaGetSymbolAddress((void**)&p_grh16, g_grh16);
    cudaGetSymbolAddress((void**)&p_z, g_z);

    cudaFuncSetAttribute(gate_mma, cudaFuncAttributeMaxDynamicSharedMemorySize, 71680);
    cudaFuncSetAttribute(cand_mma, cudaFuncAttributeMaxDynamicSharedMemorySize, 71680);
    size_t sm80  = (size_t)4 * 64 * KS80  * 2;   // 45056
    size_t sm128 = (size_t)4 * 64 * KS128 * 2;   // 69632

    // CSR build
    hist_kernel<<<(E + 255) / 256, 256>>>(dst, E);              // 0
    scan_kernel<<<1, 1024>>>(N);                                // 1
    scatter_kernel<<<(E + 255) / 256, 256>>>(src, dst, ew, E);  // 2

    int gblocks = (N + 7) / 8;
    gconv_x<<<gblocks, 256>>>(x, N);                            // 3 (ncu-profiled slot)

    // weight prep (once per launch; tiny)
    prep_w<<<(128 * KS80  + 255) / 256, 256>>>(Wg0, 128, 72, 128, KS80,  WG0H, WG0L);
    prep_w<<<(64  * KS80  + 255) / 256, 256>>>(Wc0,  64, 72,  64, KS80,  WC0H, WC0L);
    prep_w<<<(128 * KS128 + 255) / 256, 256>>>(Wg1, 128, 128, 128, KS128, WG1H, WG1L);
    prep_w<<<(64  * KS128 + 255) / 256, 256>>>(Wc1,  64, 128,  64, KS128, WC1H, WC1L);

    int rb = (N + 63) / 64;
    dim3 gate_grid(rb, 2);
    size_t N8 = (size_t)N * 8;

    for (int t = 0; t < 12; t++) {
        // ---- cell 0 ----  (gconv(h0_{t-1}) = gpair16 cols 0..63; zero at t=0)
        gate_mma<<<gate_grid, 128, sm80>>>(p_gx16 + (size_t)t * N8, 8, 4, 4,
                                           p_gpair16, 128, 64, 32,
                                           80, WG0H, WG0L,
                                           bg0, p_h0, p_z, N);
        gconv64_h16<<<gblocks, 256>>>(N);
        cand_mma<<<rb, 128, sm80>>>(p_gx16 + (size_t)t * N8, 8, 4, 4,
                                    p_grh16, 64, 32, 32,
                                    80, WC0H, WC0L,
                                    bc0, p_z, p_h0, 0, N);       // h0 <- new h0
        // ---- cell 1 ----
        gconv_dual_h16<<<gblocks, 256>>>(N);  // [gconv(h0_new) | gconv(h1)] hi/lo
        gate_mma<<<gate_grid, 128, sm128>>>(p_gpair16, 128, 64, 64,
                                            p_gpair16, 128, 64, 0,
                                            128, WG1H, WG1L,
                                            bg1, p_h1, p_z, N);
        gconv64_h16<<<gblocks, 256>>>(N);
        cand_mma<<<rb, 128, sm128>>>(p_gpair16, 128, 64, 32,
                                     p_grh16, 64, 32, 32,
                                     128, WC1H, WC1L,
                                     bc1, p_z, p_h1, 1, N);      // h1 <- new h1
    }

    out_kernel<<<gblocks, 256>>>(p_h1, Wout, bout, (float*)d_out, N);
    cleanup_kernel<<<512, 256>>>(N);
}

// round 15
// speedup vs baseline: 1.8404x; 1.3296x over previous
#include <cuda_runtime.h>
#include <cuda_fp16.h>
#include <math.h>

#define NMAX 50000
#define EMAX 800000

__device__ __forceinline__ float tanh_fast(float x) {
    float y;
    asm("tanh.approx.f32 %0, %1;" : "=f"(y) : "f"(x));
    return y;
}
__device__ __forceinline__ float sigmoid_fast(float x) {
    return 0.5f * tanh_fast(0.5f * x) + 0.5f;
}

#define MMA16816(d, a, b0_, b1_) \
    asm volatile("mma.sync.aligned.m16n8k16.row.col.f32.f16.f16.f32 " \
        "{%0,%1,%2,%3}, {%4,%5,%6,%7}, {%8,%9}, {%0,%1,%2,%3};" \
        : "+f"((d)[0]), "+f"((d)[1]), "+f"((d)[2]), "+f"((d)[3]) \
        : "r"((a)[0]), "r"((a)[1]), "r"((a)[2]), "r"((a)[3]), "r"(b0_), "r"(b1_))

// ---------------- scratch (device globals; zero-initialized at module load) ----------
__device__ __align__(16) float    g_gx[NMAX * 96];     // gconv(x) fp32, t-major [t][node][8]
__device__ __align__(16) float    g_h0[NMAX * 64];
__device__ __align__(16) float    g_h1[NMAX * 64];
__device__ __align__(16) float    g_gpair[NMAX * 128]; // [gconv(h0) | gconv(h1)] fp32
__device__ __align__(16) float    g_grh[NMAX * 64];    // gconv(r*h) fp32
__device__ __align__(16) float    g_z[NMAX * 64];
__device__ __align__(8)  __half2  g_rh16[NMAX * 32];   // r*h fp16 (gconv64 input)
__device__ __align__(16) uint2    g_hpk[NMAX * 32];    // packed {h0 half2, h1 half2} per lane
__device__ __align__(16) __half   g_w16[90112];        // pre-split, pre-transposed weights
__device__ int  g_rowptr[NMAX + 1];
__device__ int  g_off[NMAX];
__device__ __align__(8) int2 g_edge[EMAX];             // (src, w bits)

// weight table offsets (halves); per matrix: hi block [col][KS], then lo block
#define KS80  88
#define KS128 136
#define WG0H 0
#define WG0L (WG0H + 128 * KS80)
#define WC0H (WG0L + 128 * KS80)
#define WC0L (WC0H + 64 * KS80)
#define WG1H (WC0L + 64 * KS80)
#define WG1L (WG1H + 128 * KS128)
#define WC1H (WG1L + 128 * KS128)
#define WC1L (WC1H + 64 * KS128)

// NOTE: h0/h1/gpair/hpk/rowptr must be zero at entry. Zero-initialized at module
// load; cleanup_kernel (last launch) re-zeroes them.

__global__ void hist_kernel(const int* __restrict__ dst, int E) {
    int e = blockIdx.x * blockDim.x + threadIdx.x;
    if (e < E) atomicAdd(&g_rowptr[dst[e] + 1], 1);
}

__global__ void scan_kernel(int n) {
    __shared__ int buf[1024];
    __shared__ int carry;
    if (threadIdx.x == 0) carry = 0;
    __syncthreads();
    for (int base = 0; base < n + 1; base += 1024) {
        int i = base + threadIdx.x;
        int v = (i < n + 1) ? g_rowptr[i] : 0;
        buf[threadIdx.x] = v;
        __syncthreads();
        for (int ofs = 1; ofs < 1024; ofs <<= 1) {
            int t = (threadIdx.x >= ofs) ? buf[threadIdx.x - ofs] : 0;
            __syncthreads();
            buf[threadIdx.x] += t;
            __syncthreads();
        }
        int inc = buf[threadIdx.x] + carry;
        if (i < n + 1) {
            g_rowptr[i] = inc;
            if (i < n) g_off[i] = inc;
        }
        __syncthreads();
        if (threadIdx.x == 1023) carry = inc;
        __syncthreads();
    }
}

__global__ void scatter_kernel(const int* __restrict__ src, const int* __restrict__ dst,
                               const float* __restrict__ w, int E) {
    int e = blockIdx.x * blockDim.x + threadIdx.x;
    if (e < E) {
        int p = atomicAdd(&g_off[dst[e]], 1);
        g_edge[p] = make_int2(src[e], __float_as_int(w[e]));
    }
}

// ---------------- weight prep: split fp32 -> (hi, lo) fp16, transposed [col][KS] ------
__global__ void prep_w(const float* __restrict__ W, int ldw, int K, int ncols, int KS,
                       int hi_off, int lo_off) {
    int idx = blockIdx.x * blockDim.x + threadIdx.x;
    if (idx >= ncols * KS) return;
    int col = idx / KS, k = idx - col * KS;
    float v = (k < K) ? __ldg(&W[k * ldw + col]) : 0.f;
    __half hi = __float2half_rn(v);
    __half lo = __float2half_rn(v - __half2float(hi));
    g_w16[hi_off + col * KS + k] = hi;
    g_w16[lo_off + col * KS + k] = lo;
}

// ---------------- graph convolutions (warp per node, CSR) ----------------
// writes t-major fp32: g_gx[t*N*8 + node*8 + f]
__global__ void gconv_x(const float* __restrict__ x, int N) {
    int node = blockIdx.x * (blockDim.x >> 5) + (threadIdx.x >> 5);
    if (node >= N) return;
    int lane = threadIdx.x & 31;
    int s = g_rowptr[node], e = g_rowptr[node + 1];
    float a0 = 0.f, a1 = 0.f, a2 = 0.f;
    for (int i = s; i < e; i++) {
        int2 em = __ldg(&g_edge[i]);
        float w = __int_as_float(em.y);
        const float* f = x + (size_t)em.x * 96;
        a0 += w * __ldg(f + lane);
        a1 += w * __ldg(f + lane + 32);
        a2 += w * __ldg(f + lane + 64);
    }
    size_t N8 = (size_t)N * 8;
#pragma unroll
    for (int j = 0; j < 3; j++) {
        int v = lane + j * 32;
        float a = (j == 0) ? a0 : (j == 1) ? a1 : a2;
        g_gx[(size_t)(v % 12) * N8 + (size_t)node * 8 + (v / 12)] = a;
    }
}

// 64-col aggregation over fp16 table g_rh16 -> fp32 g_grh
__global__ void gconv64_h16(int N) {
    int node = blockIdx.x * (blockDim.x >> 5) + (threadIdx.x >> 5);
    if (node >= N) return;
    int lane = threadIdx.x & 31;
    int s = g_rowptr[node], e = g_rowptr[node + 1];
    float ax = 0.f, ay = 0.f;
    int i = s;
    for (; i + 3 < e; i += 4) {
        int2 e0 = __ldg(&g_edge[i]),     e1 = __ldg(&g_edge[i + 1]);
        int2 e2 = __ldg(&g_edge[i + 2]), e3 = __ldg(&g_edge[i + 3]);
        float2 f0 = __half22float2(__ldg(&g_rh16[(size_t)e0.x * 32 + lane]));
        float2 f1 = __half22float2(__ldg(&g_rh16[(size_t)e1.x * 32 + lane]));
        float2 f2 = __half22float2(__ldg(&g_rh16[(size_t)e2.x * 32 + lane]));
        float2 f3 = __half22float2(__ldg(&g_rh16[(size_t)e3.x * 32 + lane]));
        float w0 = __int_as_float(e0.y), w1 = __int_as_float(e1.y);
        float w2 = __int_as_float(e2.y), w3 = __int_as_float(e3.y);
        ax += w0 * f0.x; ay += w0 * f0.y;
        ax += w1 * f1.x; ay += w1 * f1.y;
        ax += w2 * f2.x; ay += w2 * f2.y;
        ax += w3 * f3.x; ay += w3 * f3.y;
    }
    for (; i < e; i++) {
        int2 e0 = __ldg(&g_edge[i]);
        float w0 = __int_as_float(e0.y);
        float2 f0 = __half22float2(__ldg(&g_rh16[(size_t)e0.x * 32 + lane]));
        ax += w0 * f0.x; ay += w0 * f0.y;
    }
    ((float2*)(g_grh + (size_t)node * 64))[lane] = make_float2(ax, ay);
}

// dual aggregation over packed fp16 {h0,h1} table -> fp32 gpair row of 128
__global__ void gconv_dual_h16(int N) {
    int node = blockIdx.x * (blockDim.x >> 5) + (threadIdx.x >> 5);
    if (node >= N) return;
    int lane = threadIdx.x & 31;
    int s = g_rowptr[node], e = g_rowptr[node + 1];
    float ax = 0.f, ay = 0.f, bx = 0.f, by = 0.f;
    int i = s;
    for (; i + 1 < e; i += 2) {
        int2 e0 = __ldg(&g_edge[i]), e1 = __ldg(&g_edge[i + 1]);
        uint2 p0 = __ldg(&g_hpk[(size_t)e0.x * 32 + lane]);
        uint2 p1 = __ldg(&g_hpk[(size_t)e1.x * 32 + lane]);
        float w0 = __int_as_float(e0.y), w1 = __int_as_float(e1.y);
        float2 a0 = __half22float2(*(__half2*)&p0.x), b0 = __half22float2(*(__half2*)&p0.y);
        float2 a1 = __half22float2(*(__half2*)&p1.x), b1 = __half22float2(*(__half2*)&p1.y);
        ax += w0 * a0.x; ay += w0 * a0.y; bx += w0 * b0.x; by += w0 * b0.y;
        ax += w1 * a1.x; ay += w1 * a1.y; bx += w1 * b1.x; by += w1 * b1.y;
    }
    if (i < e) {
        int2 e0 = __ldg(&g_edge[i]);
        uint2 p0 = __ldg(&g_hpk[(size_t)e0.x * 32 + lane]);
        float w0 = __int_as_float(e0.y);
        float2 a0 = __half22float2(*(__half2*)&p0.x), b0 = __half22float2(*(__half2*)&p0.y);
        ax += w0 * a0.x; ay += w0 * a0.y; bx += w0 * b0.x; by += w0 * b0.y;
    }
    ((float2*)(g_gpair + (size_t)node * 128))[lane]      = make_float2(ax, ay);
    ((float2*)(g_gpair + (size_t)node * 128 + 64))[lane] = make_float2(bx, by);
}

// ================= split-fp16 MMA GEMM, A streamed from global =================
// Block 64x64, 128 threads (4 warps 2m x 2n, warp tile 32x32).
// W staged in smem from pre-split table; A float2 loaded per-fragment, split in regs.
// D = Ahi@Whi + Ahi@Wlo + Alo@Whi (fp32-accurate; lo*lo ~2^-22 dropped).

__device__ __forceinline__ void stage_w16(unsigned* SWh_u, unsigned* SWl_u,
                                          int hi_off, int lo_off, int KS, int tid) {
    const uint4* srch = (const uint4*)(g_w16 + hi_off);
    const uint4* srcl = (const uint4*)(g_w16 + lo_off);
    uint4* dsth = (uint4*)SWh_u;
    uint4* dstl = (uint4*)SWl_u;
    int n4 = (64 * KS) >> 3;
    for (int i = tid; i < n4; i += 128) {
        dsth[i] = __ldg(&srch[i]);
        dstl[i] = __ldg(&srcl[i]);
    }
}

__device__ __forceinline__ void ldsplit(
        const float* __restrict__ A1, int lda1, int K1,
        const float* __restrict__ A2, int lda2, int K,
        int grow, int k, bool ok, unsigned& hi, unsigned& lo) {
    float2 v = make_float2(0.f, 0.f);
    if (ok && k < K) {
        v = (k < K1) ? *(const float2*)&A1[(size_t)grow * lda1 + k]
                     : *(const float2*)&A2[(size_t)grow * lda2 + (k - K1)];
    }
    __half2 h2 = __floats2half2_rn(v.x, v.y);
    float2 hf = __half22float2(h2);
    __half2 l2 = __floats2half2_rn(v.x - hf.x, v.y - hf.y);
    hi = *(unsigned*)&h2;
    lo = *(unsigned*)&l2;
}

#define MMA_MAINLOOP_DIRECT(A1, lda1, K1, A2, lda2, K, SWh, SWl, Kpad, KS, acc)     \
    for (int k0 = 0; k0 < (Kpad); k0 += 16) {                                       \
        unsigned ah[2][4], al[2][4];                                                \
        _Pragma("unroll")                                                           \
        for (int mf = 0; mf < 2; mf++) {                                            \
            int r0 = row0 + mo + mf * 16 + gid;                                     \
            bool ok0 = r0 < nrows, ok1 = (r0 + 8) < nrows;                          \
            int kk = k0 + tg * 2;                                                   \
            ldsplit(A1, lda1, K1, A2, lda2, K, r0,     kk,     ok0, ah[mf][0], al[mf][0]); \
            ldsplit(A1, lda1, K1, A2, lda2, K, r0 + 8, kk,     ok1, ah[mf][1], al[mf][1]); \
            ldsplit(A1, lda1, K1, A2, lda2, K, r0,     kk + 8, ok0, ah[mf][2], al[mf][2]); \
            ldsplit(A1, lda1, K1, A2, lda2, K, r0 + 8, kk + 8, ok1, ah[mf][3], al[mf][3]); \
        }                                                                           \
        _Pragma("unroll")                                                           \
        for (int nf = 0; nf < 4; nf++) {                                            \
            int n = no + nf * 8 + gid;                                              \
            const __half* bph = &(SWh)[n * (KS) + k0 + tg * 2];                     \
            const __half* bpl = &(SWl)[n * (KS) + k0 + tg * 2];                     \
            unsigned bh0 = *(const unsigned*)bph, bh1 = *(const unsigned*)(bph + 8);\
            unsigned bl0 = *(const unsigned*)bpl, bl1 = *(const unsigned*)(bpl + 8);\
            _Pragma("unroll")                                                       \
            for (int mf = 0; mf < 2; mf++) {                                        \
                MMA16816(acc[mf][nf], ah[mf], bh0, bh1);                            \
                MMA16816(acc[mf][nf], ah[mf], bl0, bl1);                            \
                MMA16816(acc[mf][nf], al[mf], bh0, bh1);                            \
            }                                                                       \
        }                                                                           \
    }

// gate: rz = sigmoid(A @ W + b); cy=0 -> rh16 = sig*h; cy=1 -> z
__global__ void __launch_bounds__(128) gate_mma(
        const float* __restrict__ A1, int lda1, int K1,
        const float* __restrict__ A2, int lda2, int K,
        int Kpad, int w_hi, int w_lo,
        const float* __restrict__ bias, const float* __restrict__ h,
        float* __restrict__ z, int nrows) {
    extern __shared__ __align__(16) char smraw[];
    const int KS = Kpad + 8;
    __half* SWh = (__half*)smraw;
    __half* SWl = SWh + 64 * KS;
    int tid = threadIdx.x;
    int cy = blockIdx.y;
    int row0 = blockIdx.x * 64;

    stage_w16((unsigned*)SWh, (unsigned*)SWl, w_hi + cy * 64 * KS, w_lo + cy * 64 * KS, KS, tid);
    __syncthreads();

    int lane = tid & 31, warp = tid >> 5;
    int gid = lane >> 2, tg = lane & 3;
    int mo = (warp & 1) * 32, no = (warp >> 1) * 32;
    float acc[2][4][4];
#pragma unroll
    for (int mf = 0; mf < 2; mf++)
#pragma unroll
        for (int nf = 0; nf < 4; nf++)
#pragma unroll
            for (int q = 0; q < 4; q++) acc[mf][nf][q] = 0.f;

    MMA_MAINLOOP_DIRECT(A1, lda1, K1, A2, lda2, K, SWh, SWl, Kpad, KS, acc)

#pragma unroll
    for (int mf = 0; mf < 2; mf++) {
#pragma unroll
        for (int nf = 0; nf < 4; nf++) {
            int j = no + nf * 8 + tg * 2;
            float b0 = __ldg(&bias[cy * 64 + j]);
            float b1 = __ldg(&bias[cy * 64 + j + 1]);
#pragma unroll
            for (int rr = 0; rr < 2; rr++) {
                int grow = row0 + mo + mf * 16 + gid + rr * 8;
                if (grow >= nrows) continue;
                float v0 = sigmoid_fast(acc[mf][nf][rr * 2 + 0] + b0);
                float v1 = sigmoid_fast(acc[mf][nf][rr * 2 + 1] + b1);
                if (cy == 0) {
                    float2 h2 = *(const float2*)&h[(size_t)grow * 64 + j];
                    g_rh16[(size_t)grow * 32 + (j >> 1)] =
                        __floats2half2_rn(v0 * h2.x, v1 * h2.y);
                } else {
                    *(float2*)&z[(size_t)grow * 64 + j] = make_float2(v0, v1);
                }
            }
        }
    }
}

// cand: c = tanh(A @ W + b); h = z*h + (1-z)*c; fp16 copy into hpk slot
__global__ void __launch_bounds__(128) cand_mma(
        const float* __restrict__ A1, int lda1, int K1,
        const float* __restrict__ A2, int lda2, int K,
        int Kpad, int w_hi, int w_lo,
        const float* __restrict__ bias, const float* __restrict__ z,
        float* __restrict__ h, int slot, int nrows) {
    extern __shared__ __align__(16) char smraw[];
    const int KS = Kpad + 8;
    __half* SWh = (__half*)smraw;
    __half* SWl = SWh + 64 * KS;
    int tid = threadIdx.x;
    int row0 = blockIdx.x * 64;

    stage_w16((unsigned*)SWh, (unsigned*)SWl, w_hi, w_lo, KS, tid);
    __syncthreads();

    int lane = tid & 31, warp = tid >> 5;
    int gid = lane >> 2, tg = lane & 3;
    int mo = (warp & 1) * 32, no = (warp >> 1) * 32;
    float acc[2][4][4];
#pragma unroll
    for (int mf = 0; mf < 2; mf++)
#pragma unroll
        for (int nf = 0; nf < 4; nf++)
#pragma unroll
            for (int q = 0; q < 4; q++) acc[mf][nf][q] = 0.f;

    MMA_MAINLOOP_DIRECT(A1, lda1, K1, A2, lda2, K, SWh, SWl, Kpad, KS, acc)

#pragma unroll
    for (int mf = 0; mf < 2; mf++) {
#pragma unroll
        for (int nf = 0; nf < 4; nf++) {
            int j = no + nf * 8 + tg * 2;
            float b0 = __ldg(&bias[j]);
            float b1 = __ldg(&bias[j + 1]);
#pragma unroll
            for (int rr = 0; rr < 2; rr++) {
                int grow = row0 + mo + mf * 16 + gid + rr * 8;
                if (grow >= nrows) continue;
                float c0 = tanh_fast(acc[mf][nf][rr * 2 + 0] + b0);
                float c1 = tanh_fast(acc[mf][nf][rr * 2 + 1] + b1);
                float2 z2 = *(const float2*)&z[(size_t)grow * 64 + j];
                float2 h2 = *(const float2*)&h[(size_t)grow * 64 + j];
                float n0 = z2.x * h2.x + (1.f - z2.x) * c0;
                float n1 = z2.y * h2.y + (1.f - z2.y) * c1;
                *(float2*)&h[(size_t)grow * 64 + j] = make_float2(n0, n1);
                __half2 q = __floats2half2_rn(n0, n1);
                unsigned* hp = (unsigned*)&g_hpk[(size_t)grow * 32 + (j >> 1)];
                hp[slot] = *(unsigned*)&q;
            }
        }
    }
}

// ---------------- output: out = h1 @ Wout + bout ----------------
__global__ void out_kernel(const float* __restrict__ h1, const float* __restrict__ Wout,
                           const float* __restrict__ bout, float* __restrict__ out, int N) {
    int node = blockIdx.x * (blockDim.x >> 5) + (threadIdx.x >> 5);
    if (node >= N) return;
    int lane = threadIdx.x & 31;
    float v = h1[(size_t)node * 64 + lane] * __ldg(&Wout[lane]) +
              h1[(size_t)node * 64 + lane + 32] * __ldg(&Wout[lane + 32]);
#pragma unroll
    for (int o = 16; o > 0; o >>= 1) v += __shfl_xor_sync(0xffffffffu, v, o);
    if (lane == 0) out[node] = v + bout[0];
}

// ---------------- cleanup: restore zero-state invariant ----------------
__global__ void cleanup_kernel(int N) {
    int stride = gridDim.x * blockDim.x;
    for (int i = blockIdx.x * blockDim.x + threadIdx.x; i < N * 128; i += stride) {
        g_gpair[i] = 0.f;
        if (i < N * 64) { g_h0[i] = 0.f; g_h1[i] = 0.f; }
        if (i < N * 32) g_hpk[i] = make_uint2(0u, 0u);
        if (i < N + 1) g_rowptr[i] = 0;
    }
}

// ---------------- launch ----------------
extern "C" void kernel_launch(void* const* d_in, const int* in_sizes, int n_in,
                              void* d_out, int out_size) {
    const float* x   = (const float*)d_in[0];
    const int*   ei  = (const int*)d_in[1];
    const float* ew  = (const float*)d_in[2];
    const float* Wg0 = (const float*)d_in[3];
    const float* bg0 = (const float*)d_in[4];
    const float* Wc0 = (const float*)d_in[5];
    const float* bc0 = (const float*)d_in[6];
    const float* Wg1 = (const float*)d_in[7];
    const float* bg1 = (const float*)d_in[8];
    const float* Wc1 = (const float*)d_in[9];
    const float* bc1 = (const float*)d_in[10];
    const float* Wout = (const float*)d_in[11];
    const float* bout = (const float*)d_in[12];

    int N = in_sizes[0] / 96;   // F=8, T=12
    int E = in_sizes[2];
    if (N > NMAX || E > EMAX) return;
    const int* src = ei;
    const int* dst = ei + E;

    float *p_gx, *p_h0, *p_h1, *p_gpair, *p_grh, *p_z;
    cudaGetSymbolAddress((void**)&p_gx, g_gx);
    cudaGetSymbolAddress((void**)&p_h0, g_h0);
    cudaGetSymbolAddress((void**)&p_h1, g_h1);
    cudaGetSymbolAddress((void**)&p_gpair, g_gpair);
    cudaGetSymbolAddress((void**)&p_grh, g_grh);
    cudaGetSymbolAddress((void**)&p_z, g_z);

    cudaFuncSetAttribute(gate_mma, cudaFuncAttributeMaxDynamicSharedMemorySize, 36864);
    cudaFuncSetAttribute(cand_mma, cudaFuncAttributeMaxDynamicSharedMemorySize, 36864);
    size_t wsm80  = (size_t)2 * 64 * KS80  * 2;   // 22528
    size_t wsm128 = (size_t)2 * 64 * KS128 * 2;   // 34816

    // CSR build
    hist_kernel<<<(E + 255) / 256, 256>>>(dst, E);              // 0
    scan_kernel<<<1, 1024>>>(N);                                // 1
    scatter_kernel<<<(E + 255) / 256, 256>>>(src, dst, ew, E);  // 2

    int gblocks = (N + 7) / 8;
    gconv_x<<<gblocks, 256>>>(x, N);                            // 3 (ncu-profiled slot)

    // weight prep (once per launch; tiny)
    prep_w<<<(128 * KS80  + 255) / 256, 256>>>(Wg0, 128, 72, 128, KS80,  WG0H, WG0L);
    prep_w<<<(64  * KS80  + 255) / 256, 256>>>(Wc0,  64, 72,  64, KS80,  WC0H, WC0L);
    prep_w<<<(128 * KS128 + 255) / 256, 256>>>(Wg1, 128, 128, 128, KS128, WG1H, WG1L);
    prep_w<<<(64  * KS128 + 255) / 256, 256>>>(Wc1,  64, 128,  64, KS128, WC1H, WC1L);

    int rb = (N + 63) / 64;
    dim3 gate_grid(rb, 2);
    size_t N8 = (size_t)N * 8;

    for (int t = 0; t < 12; t++) {
        // ---- cell 0 ----  (gconv(h0_{t-1}) = gpair cols 0..63; zero at t=0)
        gate_mma<<<gate_grid, 128, wsm80>>>(p_gx + (size_t)t * N8, 8, 8,
                                            p_gpair, 128, 72,
                                            80, WG0H, WG0L,
                                            bg0, p_h0, p_z, N);
        gconv64_h16<<<gblocks, 256>>>(N);
        cand_mma<<<rb, 128, wsm80>>>(p_gx + (size_t)t * N8, 8, 8,
                                     p_grh, 64, 72,
                                     80, WC0H, WC0L,
                                     bc0, p_z, p_h0, 0, N);      // h0 <- new h0
        // ---- cell 1 ----
        gconv_dual_h16<<<gblocks, 256>>>(N);  // [gconv(h0_new) | gconv(h1)] fp32
        gate_mma<<<gate_grid, 128, wsm128>>>(p_gpair, 128, 128,
                                             p_gpair, 128, 128,
                                             128, WG1H, WG1L,
                                             bg1, p_h1, p_z, N);
        gconv64_h16<<<gblocks, 256>>>(N);
        cand_mma<<<rb, 128, wsm128>>>(p_gpair, 128, 64,
                                      p_grh, 64, 128,
                                      128, WC1H, WC1L,
                                      bc1, p_z, p_h1, 1, N);     // h1 <- new h1
    }

    out_kernel<<<gblocks, 256>>>(p_h1, Wout, bout, (float*)d_out, N);
    cleanup_kernel<<<512, 256>>>(N);
}